// round 13
// baseline (speedup 1.0000x reference)
#include <cuda_runtime.h>
#include <cuda_bf16.h>
#include <cstdint>

// VQ codebook lookup: int8 tensor-core approx GEMM (per-row symmetric quant)
// -> candidate capture -> exact fp32 reference-rounded rescore (+ gather).
//   dist[n,q] = fl( fl(x_sq[n] - fl(2*xw[n,q])) + w_sq[q] ), argmin, ties->lowest q.
// Family-common PTX only (ldmatrix + mma.sync m16n8k32 s8).
//
// Error calibration: int8 per-row quant gives approx-dist error sigma ~5e-4;
// MARGIN=0.006 is ~12 sigma of the error but only ~0.13 sigma of the data
// spread -> capture is safe AND sparse. Exact rescore reproduces the
// reference argmin bit-for-bit (validated R4/R10).

#define E_DIM    512
#define N_MAX    16384
#define Q_MAX    8192
#define M_T      128
#define NQ_T     128
#define KB       128          // int8 k elements per stage (128 B rows)
#define THREADS  256
#define MARGIN   0.006f
#define CAND_CAP 64

#define A_BYTES     (M_T * E_DIM)            // 65536: resident A (int8)
#define BSTAGE      16384                     // one B tile (128 x 128 int8)
#define NSTAGE      3
#define DSMEM_BYTES (A_BYTES + NSTAGE * BSTAGE)   // 114688

__device__ float g_wsq[Q_MAX];
__device__ float g_xsq[N_MAX];
__device__ float g_xscale[N_MAX];
__device__ float g_wscale[Q_MAX];
__device__ int8_t g_xq[(size_t)N_MAX * E_DIM];
__device__ int8_t g_wq[(size_t)Q_MAX * E_DIM];
__device__ int g_cand[(size_t)N_MAX * CAND_CAP];
__device__ int g_ccnt[N_MAX];

// ---------------- PTX helpers ----------------------------------------------
__device__ __forceinline__ uint32_t smem_u32(const void* p) {
    uint32_t a;
    asm("{ .reg .u64 t; cvta.to.shared.u64 t, %1; cvt.u32.u64 %0, t; }" : "=r"(a) : "l"(p));
    return a;
}
#define CP16(dst, src) \
    asm volatile("cp.async.cg.shared.global [%0], [%1], 16;" :: "r"(dst), "l"(src))
#define CP_COMMIT() asm volatile("cp.async.commit_group;" ::: "memory")
#define CP_WAIT0()  asm volatile("cp.async.wait_group 0;" ::: "memory")
#define CP_WAIT1()  asm volatile("cp.async.wait_group 1;" ::: "memory")

__device__ __forceinline__ void ldsm4(uint32_t& r0, uint32_t& r1, uint32_t& r2,
                                      uint32_t& r3, uint32_t addr) {
    asm volatile("ldmatrix.sync.aligned.m8n8.x4.shared.b16 {%0,%1,%2,%3}, [%4];"
                 : "=r"(r0), "=r"(r1), "=r"(r2), "=r"(r3) : "r"(addr));
}
__device__ __forceinline__ void mma16832s8(int* c, const uint32_t* a,
                                           uint32_t b0, uint32_t b1) {
    asm volatile(
        "mma.sync.aligned.m16n8k32.row.col.s32.s8.s8.s32 "
        "{%0,%1,%2,%3}, {%4,%5,%6,%7}, {%8,%9}, {%0,%1,%2,%3};"
        : "+r"(c[0]), "+r"(c[1]), "+r"(c[2]), "+r"(c[3])
        : "r"(a[0]), "r"(a[1]), "r"(a[2]), "r"(a[3]), "r"(b0), "r"(b1));
}

// ---------------------------------------------------------------------------
// Prep pass 1: bit-exact sequential row sum-of-squares + row max -> scale.
// ---------------------------------------------------------------------------
__global__ __launch_bounds__(128) void prep_kernel(const float* __restrict__ a,
                                                   int nrows, int which)
{
    __shared__ float tile[128][66];
    const int t = threadIdx.x;
    const int r0 = blockIdx.x * 128;

    float s = 0.f;
    float m = 0.f;
    for (int c0 = 0; c0 < E_DIM; c0 += 64) {
#pragma unroll
        for (int i = 0; i < 32; i++) {
            int lin = i * 128 + t;
            int c = (lin & 31) * 2;
            int r = lin >> 5;
            float2 v = *(const float2*)&a[(size_t)(r0 + r) * E_DIM + c0 + c];
            tile[r][c] = v.x;
            tile[r][c + 1] = v.y;
        }
        __syncthreads();
#pragma unroll
        for (int c = 0; c < 64; c++) {
            float v = tile[t][c];
            s = __fadd_rn(s, __fmul_rn(v, v));   // strictly sequential, no FMA
            m = fmaxf(m, fabsf(v));
        }
        __syncthreads();
    }
    if (r0 + t < nrows) {
        float sc = (m > 0.f) ? (m / 127.0f) : 1.0f;
        if (which == 0) { g_xsq[r0 + t] = s; g_xscale[r0 + t] = sc; }
        else            { g_wsq[r0 + t] = s; g_wscale[r0 + t] = sc; }
    }
}

// ---------------------------------------------------------------------------
// Prep pass 2: int8 quantization (8 elems per thread).
// ---------------------------------------------------------------------------
__global__ __launch_bounds__(256) void quant_kernel(const float* __restrict__ a,
                                                    long long n8, int which)
{
    long long i = (long long)blockIdx.x * blockDim.x + threadIdx.x;
    if (i >= n8) return;
    int row = (int)(i >> 6);                  // 64 8-elem groups per 512-row
    float inv = 1.0f / (which ? g_wscale[row] : g_xscale[row]);
    const float4* src = (const float4*)(a + i * 8);
    float4 v0 = src[0], v1 = src[1];
    int q[8];
    q[0] = __float2int_rn(v0.x * inv); q[1] = __float2int_rn(v0.y * inv);
    q[2] = __float2int_rn(v0.z * inv); q[3] = __float2int_rn(v0.w * inv);
    q[4] = __float2int_rn(v1.x * inv); q[5] = __float2int_rn(v1.y * inv);
    q[6] = __float2int_rn(v1.z * inv); q[7] = __float2int_rn(v1.w * inv);
    uint2 pk;
    uint32_t lo = 0, hi = 0;
#pragma unroll
    for (int j = 0; j < 4; j++) {
        int c = max(-127, min(127, q[j]));
        lo |= ((uint32_t)(uint8_t)(int8_t)c) << (j * 8);
    }
#pragma unroll
    for (int j = 0; j < 4; j++) {
        int c = max(-127, min(127, q[4 + j]));
        hi |= ((uint32_t)(uint8_t)(int8_t)c) << (j * 8);
    }
    pk.x = lo; pk.y = hi;
    uint2* dst = (uint2*)(which ? g_wq : g_xq);
    dst[i] = pk;
}

// ---------------------------------------------------------------------------
// Approx GEMM (int8 IMMA), A resident, 3-stage B ring, candidate capture.
// ---------------------------------------------------------------------------
__global__ __launch_bounds__(THREADS) void vq_approx_kernel(int Q)
{
    extern __shared__ char smem[];
    __shared__ float xsq_s[M_T];
    __shared__ float xscale_s[M_T];
    __shared__ float wsq_s[NQ_T];
    __shared__ float wscale_s[NQ_T];
    __shared__ int rows_min[M_T];
    __shared__ int cand_cnt[M_T];

    const int tid  = threadIdx.x;
    const int lane = tid & 31;
    const int wid  = tid >> 5;
    const int wm   = wid & 3;
    const int wn   = wid >> 2;
    const int n0   = blockIdx.x * M_T;

    const uint32_t sbase = smem_u32(smem);      // A: 4 sub-tiles of 16KB
    const uint32_t bbase = sbase + A_BYTES;     // B ring: 3 stages of 16KB

    if (tid < M_T) {
        xsq_s[tid]    = g_xsq[n0 + tid];
        xscale_s[tid] = g_xscale[n0 + tid];
        rows_min[tid] = 0x7f800000;
        cand_cnt[tid] = 0;
    }

    // ---- prologue: resident A (one group), then B tiles 0 and 1 ----
#pragma unroll
    for (int kb = 0; kb < 4; kb++) {
#pragma unroll
        for (int i = 0; i < 4; i++) {
            int idx = tid + i * THREADS;
            int r = idx >> 3, c8 = idx & 7;
            uint32_t off = r * 128 + c8 * 16;
            uint32_t sw = off ^ ((off >> 3) & 0x70);
            CP16(sbase + kb * BSTAGE + sw,
                 &g_xq[(size_t)(n0 + r) * E_DIM + kb * KB + c8 * 16]);
        }
    }
    CP_COMMIT();
#pragma unroll
    for (int j = 0; j < 2; j++) {
#pragma unroll
        for (int i = 0; i < 4; i++) {
            int idx = tid + i * THREADS;
            int r = idx >> 3, c8 = idx & 7;
            uint32_t off = r * 128 + c8 * 16;
            uint32_t sw = off ^ ((off >> 3) & 0x70);
            CP16(bbase + j * BSTAGE + sw,
                 &g_wq[(size_t)r * E_DIM + (j & 3) * KB + c8 * 16]);  // q0=0 for j<2
        }
        CP_COMMIT();
    }

    // ldmatrix offsets: identical byte geometry to the validated bf16 path
    // (16B chunks; XOR the ks*32 step into the swizzled address).
    uint32_t aOff[2], bOff[4];
#pragma unroll
    for (int mt = 0; mt < 2; mt++) {
        int row = wm * 32 + mt * 16 + (lane & 15);
        int kc  = (lane & 16) ? 16 : 0;
        uint32_t off = row * 128 + kc;
        aOff[mt] = off ^ ((off >> 3) & 0x70);
    }
#pragma unroll
    for (int bt = 0; bt < 4; bt++) {
        int row = wn * 64 + bt * 16 + ((lane & 16) ? 8 : 0) + (lane & 7);
        int kc  = (lane & 8) ? 16 : 0;
        uint32_t off = row * 128 + kc;
        bOff[bt] = off ^ ((off >> 3) & 0x70);
    }

    const int rbase = wm * 32 + (lane >> 2);
    const int cbase = wn * 64 + 2 * (lane & 3);
    const int TOTAL = (Q / NQ_T) * 4;           // 256 B tiles

    int acc[2][8][4];

    for (int it = 0; it < TOTAL; it++) {
        const int kb = it & 3;
        const int qc = it >> 2;
        const int q0 = qc * NQ_T;

        if (it + 1 < TOTAL) CP_WAIT1(); else CP_WAIT0();
        __syncthreads();

        if (kb == 0) {
            if (tid < NQ_T) {
                wsq_s[tid]    = g_wsq[q0 + tid];
                wscale_s[tid] = g_wscale[q0 + tid];
            }
#pragma unroll
            for (int mt = 0; mt < 2; mt++)
#pragma unroll
                for (int nt = 0; nt < 8; nt++)
#pragma unroll
                    for (int k = 0; k < 4; k++) acc[mt][nt][k] = 0;
        }

        // issue B tile it+2 into stage (it+2)%3
        if (it + 2 < TOTAL) {
            const int j = it + 2;
            const int jq0 = (j >> 2) * NQ_T;
            const int jkb = j & 3;
            const uint32_t st = bbase + (j % NSTAGE) * BSTAGE;
#pragma unroll
            for (int i = 0; i < 4; i++) {
                int idx = tid + i * THREADS;
                int r = idx >> 3, c8 = idx & 7;
                uint32_t off = r * 128 + c8 * 16;
                uint32_t sw = off ^ ((off >> 3) & 0x70);
                CP16(st + sw,
                     &g_wq[(size_t)(jq0 + r) * E_DIM + jkb * KB + c8 * 16]);
            }
            CP_COMMIT();
        }

        const uint32_t aB = sbase + kb * BSTAGE;
        const uint32_t bB = bbase + (it % NSTAGE) * BSTAGE;
#pragma unroll
        for (int ks = 0; ks < 4; ks++) {
            uint32_t af[2][4];
#pragma unroll
            for (int mt = 0; mt < 2; mt++)
                ldsm4(af[mt][0], af[mt][1], af[mt][2], af[mt][3],
                      aB + (aOff[mt] ^ (ks * 32)));
            uint32_t bf[4][4];
#pragma unroll
            for (int bt = 0; bt < 4; bt++)
                ldsm4(bf[bt][0], bf[bt][1], bf[bt][2], bf[bt][3],
                      bB + (bOff[bt] ^ (ks * 32)));
#pragma unroll
            for (int mt = 0; mt < 2; mt++)
#pragma unroll
                for (int nt = 0; nt < 8; nt++)
                    mma16832s8(acc[mt][nt], af[mt],
                               bf[nt >> 1][(nt & 1) * 2],
                               bf[nt >> 1][(nt & 1) * 2 + 1]);
        }

        if (kb == 3) {
            // ---- epilogue: dist (descaled), running row-min, capture ----
            float lmin[4] = {3.4e38f, 3.4e38f, 3.4e38f, 3.4e38f};
#pragma unroll
            for (int mt = 0; mt < 2; mt++) {
                int r0i = rbase + mt * 16, r1i = r0i + 8;
                float xa = xsq_s[r0i], xb = xsq_s[r1i];
                float s2a = 2.f * xscale_s[r0i], s2b = 2.f * xscale_s[r1i];
#pragma unroll
                for (int nt = 0; nt < 8; nt++) {
                    int* c = acc[mt][nt];
                    int col = cbase + nt * 8;
                    float wa = wsq_s[col], wb = wsq_s[col + 1];
                    float swa = wscale_s[col], swb = wscale_s[col + 1];
                    float d0 = fmaf(-s2a * swa, (float)c[0], xa + wa);
                    float d1 = fmaf(-s2a * swb, (float)c[1], xa + wb);
                    float d2 = fmaf(-s2b * swa, (float)c[2], xb + wa);
                    float d3 = fmaf(-s2b * swb, (float)c[3], xb + wb);
                    lmin[mt * 2]     = fminf(lmin[mt * 2],     fminf(d0, d1));
                    lmin[mt * 2 + 1] = fminf(lmin[mt * 2 + 1], fminf(d2, d3));
                }
            }
#pragma unroll
            for (int g = 0; g < 4; g++) {
                int row = rbase + (g >> 1) * 16 + (g & 1) * 8;
                atomicMin(&rows_min[row], __float_as_int(lmin[g]));
            }
            __syncthreads();

#pragma unroll
            for (int mt = 0; mt < 2; mt++) {
                int r0i = rbase + mt * 16, r1i = r0i + 8;
                float xa = xsq_s[r0i], xb = xsq_s[r1i];
                float s2a = 2.f * xscale_s[r0i], s2b = 2.f * xscale_s[r1i];
                float thr0 = __int_as_float(rows_min[r0i]) + MARGIN;
                float thr1 = __int_as_float(rows_min[r1i]) + MARGIN;
                if (lmin[mt * 2] <= thr0 || lmin[mt * 2 + 1] <= thr1) {
#pragma unroll
                    for (int nt = 0; nt < 8; nt++) {
                        int* c = acc[mt][nt];
                        int col = cbase + nt * 8;
                        float wa = wsq_s[col], wb = wsq_s[col + 1];
                        float swa = wscale_s[col], swb = wscale_s[col + 1];
                        float d0 = fmaf(-s2a * swa, (float)c[0], xa + wa);
                        float d1 = fmaf(-s2a * swb, (float)c[1], xa + wb);
                        float d2 = fmaf(-s2b * swa, (float)c[2], xb + wa);
                        float d3 = fmaf(-s2b * swb, (float)c[3], xb + wb);
                        if (d0 <= thr0) {
                            int p = atomicAdd(&cand_cnt[r0i], 1);
                            if (p < CAND_CAP)
                                g_cand[(size_t)(n0 + r0i) * CAND_CAP + p] = q0 + col;
                        }
                        if (d1 <= thr0) {
                            int p = atomicAdd(&cand_cnt[r0i], 1);
                            if (p < CAND_CAP)
                                g_cand[(size_t)(n0 + r0i) * CAND_CAP + p] = q0 + col + 1;
                        }
                        if (d2 <= thr1) {
                            int p = atomicAdd(&cand_cnt[r1i], 1);
                            if (p < CAND_CAP)
                                g_cand[(size_t)(n0 + r1i) * CAND_CAP + p] = q0 + col;
                        }
                        if (d3 <= thr1) {
                            int p = atomicAdd(&cand_cnt[r1i], 1);
                            if (p < CAND_CAP)
                                g_cand[(size_t)(n0 + r1i) * CAND_CAP + p] = q0 + col + 1;
                        }
                    }
                }
            }
            // next loop-top __syncthreads orders capture vs wsq_s overwrite
        }
    }

    __syncthreads();
    if (tid < M_T) g_ccnt[n0 + tid] = cand_cnt[tid];
}

// ---------------------------------------------------------------------------
// Exact rescore (reference-rounded) + gather. One warp per row.
// ---------------------------------------------------------------------------
__device__ __forceinline__ float warp_dot512(const float* __restrict__ xr,
                                             const float* __restrict__ wr,
                                             int lane)
{
    float s = 0.f;
#pragma unroll
    for (int k = 0; k < 16; k++)
        s = __fmaf_rn(xr[lane + k * 32], wr[lane + k * 32], s);
#pragma unroll
    for (int o = 16; o; o >>= 1) s += __shfl_xor_sync(0xffffffffu, s, o);
    return s;
}

__global__ __launch_bounds__(256) void rescore_kernel(
    const float* __restrict__ x, const float* __restrict__ w,
    float* __restrict__ out, float* __restrict__ out_idx,
    int write_idx, int Q)
{
    const int lane = threadIdx.x & 31;
    const int row  = blockIdx.x * 8 + (threadIdx.x >> 5);
    const float xsq = g_xsq[row];
    const float* xr = x + (size_t)row * E_DIM;

    float best = 3.4e38f;
    int   bq   = 0x7fffffff;
    int cnt = g_ccnt[row];

    if (cnt <= CAND_CAP) {
        for (int i = 0; i < cnt; i++) {
            int q = g_cand[(size_t)row * CAND_CAP + i];
            float xw = warp_dot512(xr, w + (size_t)q * E_DIM, lane);
            float t1 = __fadd_rn(xsq, -__fmul_rn(2.0f, xw));
            float d  = __fadd_rn(t1, g_wsq[q]);
            if (d < best || (d == best && q < bq)) { best = d; bq = q; }
        }
    } else {
        // overflow fallback (unreachable in practice): exact full scan.
        for (int q = 0; q < Q; q++) {
            float xw = warp_dot512(xr, w + (size_t)q * E_DIM, lane);
            float t1 = __fadd_rn(xsq, -__fmul_rn(2.0f, xw));
            float d  = __fadd_rn(t1, g_wsq[q]);
            if (d < best) { best = d; bq = q; }
        }
    }

    if (write_idx && lane == 0) out_idx[row] = (float)bq;

    const float4* wr4 = (const float4*)(w + (size_t)bq * E_DIM);
    float4* o4 = (float4*)(out + (size_t)row * E_DIM);
#pragma unroll
    for (int c = lane; c < E_DIM / 4; c += 32) o4[c] = wr4[c];
}

// ---------------------------------------------------------------------------
extern "C" void kernel_launch(void* const* d_in, const int* in_sizes, int n_in,
                              void* d_out, int out_size)
{
    const float* x = (const float*)d_in[0];
    const float* w = (const float*)d_in[1];
    float* out = (float*)d_out;

    const int E = E_DIM;
    const int N = in_sizes[0] / E;   // 16384
    const int Q = in_sizes[1] / E;   // 8192

    const long long NE = (long long)N * E;
    const long long QE = (long long)Q * E;
    int write_idx = (out_size >= NE + N) ? 1 : 0;
    float* out_idx = out + NE;

    cudaFuncSetAttribute(vq_approx_kernel,
                         cudaFuncAttributeMaxDynamicSharedMemorySize, DSMEM_BYTES);

    prep_kernel<<<N / 128, 128>>>(x, N, 0);
    prep_kernel<<<Q / 128, 128>>>(w, Q, 1);
    quant_kernel<<<(int)(NE / 8 / 256), 256>>>(x, NE / 8, 0);
    quant_kernel<<<(int)(QE / 8 / 256), 256>>>(w, QE / 8, 1);
    vq_approx_kernel<<<N / M_T, THREADS, DSMEM_BYTES>>>(Q);
    rescore_kernel<<<N / 8, 256>>>(x, w, out, out_idx, write_idx, Q);
}

// round 14
// speedup vs baseline: 2.5417x; 2.5417x over previous
#include <cuda_runtime.h>
#include <cuda_bf16.h>
#include <cstdint>

// VQ codebook lookup: bf16 tensor-core approx GEMM -> candidate capture ->
// exact fp32 reference-rounded rescore (+ gather).
//   dist[n,q] = fl( fl(x_sq[n] - fl(2*xw[n,q])) + w_sq[q] ), argmin, ties->lowest q.
// Family-common PTX only (ldmatrix + mma.sync m16n8k16 bf16) — R13 showed
// legacy IMMA (s8) runs ~4x slower per instruction on sm_103a; bf16 HMMA is
// the fastest reachable tensor path in this harness.
//
// R14: 6-stage B ring with paired tiles (one sync + one wait per 2 tiles,
// issue at loop top with 2-pair lookahead), merged prep launch.

#define E_DIM    512
#define N_MAX    16384
#define Q_MAX    8192
#define M_T      128
#define NQ_T     128
#define KB       64
#define THREADS  256
#define MARGIN   0.008f
#define CAND_CAP 64

#define A_BYTES     (M_T * E_DIM * 2)        // 131072: resident A
#define BSTAGE      16384                     // one B tile (128 x 64 bf16)
#define NSTAGE      6
#define DSMEM_BYTES (A_BYTES + NSTAGE * BSTAGE)   // 229376 (fits 227KB optin)

__device__ float g_wsq[Q_MAX];
__device__ float g_xsq[N_MAX];
__device__ __nv_bfloat16 g_xh[(size_t)N_MAX * E_DIM];
__device__ __nv_bfloat16 g_wh[(size_t)Q_MAX * E_DIM];
__device__ int g_cand[(size_t)N_MAX * CAND_CAP];
__device__ int g_ccnt[N_MAX];

// ---------------- PTX helpers ----------------------------------------------
__device__ __forceinline__ uint32_t smem_u32(const void* p) {
    uint32_t a;
    asm("{ .reg .u64 t; cvta.to.shared.u64 t, %1; cvt.u32.u64 %0, t; }" : "=r"(a) : "l"(p));
    return a;
}
#define CP16(dst, src) \
    asm volatile("cp.async.cg.shared.global [%0], [%1], 16;" :: "r"(dst), "l"(src))
#define CP_COMMIT() asm volatile("cp.async.commit_group;" ::: "memory")
#define CP_WAIT0()  asm volatile("cp.async.wait_group 0;" ::: "memory")
#define CP_WAIT1()  asm volatile("cp.async.wait_group 1;" ::: "memory")

__device__ __forceinline__ void ldsm4(uint32_t& r0, uint32_t& r1, uint32_t& r2,
                                      uint32_t& r3, uint32_t addr) {
    asm volatile("ldmatrix.sync.aligned.m8n8.x4.shared.b16 {%0,%1,%2,%3}, [%4];"
                 : "=r"(r0), "=r"(r1), "=r"(r2), "=r"(r3) : "r"(addr));
}
__device__ __forceinline__ void mma16816(float* c, const uint32_t* a,
                                         uint32_t b0, uint32_t b1) {
    asm volatile(
        "mma.sync.aligned.m16n8k16.row.col.f32.bf16.bf16.f32 "
        "{%0,%1,%2,%3}, {%4,%5,%6,%7}, {%8,%9}, {%0,%1,%2,%3};"
        : "+f"(c[0]), "+f"(c[1]), "+f"(c[2]), "+f"(c[3])
        : "r"(a[0]), "r"(a[1]), "r"(a[2]), "r"(a[3]), "r"(b0), "r"(b1));
}

// ---------------------------------------------------------------------------
// Prep (merged): bf16 convert + bit-exact sequential row sum-of-squares.
// Blocks [0, nxb) process x; blocks [nxb, nxb+nwb) process w.
// ---------------------------------------------------------------------------
__global__ __launch_bounds__(128) void prep_kernel(const float* __restrict__ x,
                                                   const float* __restrict__ w,
                                                   int nxb)
{
    __shared__ float tile[128][66];
    const int t = threadIdx.x;
    const int b = blockIdx.x;
    const int which = (b >= nxb) ? 1 : 0;
    const float* a = which ? w : x;
    const int r0 = (which ? (b - nxb) : b) * 128;
    __nv_bfloat16* gbf = which ? g_wh : g_xh;

    float s = 0.f;
    for (int c0 = 0; c0 < E_DIM; c0 += 64) {
#pragma unroll
        for (int i = 0; i < 32; i++) {
            int lin = i * 128 + t;
            int c = (lin & 31) * 2;
            int r = lin >> 5;
            float2 v = *(const float2*)&a[(size_t)(r0 + r) * E_DIM + c0 + c];
            tile[r][c] = v.x;
            tile[r][c + 1] = v.y;
            __nv_bfloat162 pk = __floats2bfloat162_rn(v.x, v.y);
            *(uint32_t*)&gbf[(size_t)(r0 + r) * E_DIM + c0 + c] = *(uint32_t*)&pk;
        }
        __syncthreads();
#pragma unroll
        for (int c = 0; c < 64; c++) {
            float v = tile[t][c];
            s = __fadd_rn(s, __fmul_rn(v, v));   // strictly sequential, no FMA
        }
        __syncthreads();
    }
    if (which == 0) g_xsq[r0 + t] = s;
    else            g_wsq[r0 + t] = s;
}

// ---------------------------------------------------------------------------
// Approx GEMM (bf16 HMMA), A resident, 6-stage paired B ring, capture.
// ---------------------------------------------------------------------------
__global__ __launch_bounds__(THREADS) void vq_approx_kernel(int Q)
{
    extern __shared__ char smem[];
    __shared__ float xsq_s[M_T];
    __shared__ float wsq_s[NQ_T];
    __shared__ int rows_min[M_T];
    __shared__ int cand_cnt[M_T];

    const int tid  = threadIdx.x;
    const int lane = tid & 31;
    const int wid  = tid >> 5;
    const int wm   = wid & 3;
    const int wn   = wid >> 2;
    const int n0   = blockIdx.x * M_T;

    const uint32_t sbase = smem_u32(smem);      // A: 8 sub-tiles of 16KB
    const uint32_t bbase = sbase + A_BYTES;     // B ring: 6 stages of 16KB

    if (tid < M_T) {
        xsq_s[tid]    = g_xsq[n0 + tid];
        rows_min[tid] = 0x7f800000;
        cand_cnt[tid] = 0;
    }

    // ---- prologue: resident A (1 group), then B pairs 0 and 1 (tiles 0..3) --
#pragma unroll
    for (int kb = 0; kb < 8; kb++) {
#pragma unroll
        for (int i = 0; i < 4; i++) {
            int idx = tid + i * THREADS;
            int r = idx >> 3, c8 = idx & 7;
            uint32_t off = r * 128 + c8 * 16;
            uint32_t sw = off ^ ((off >> 3) & 0x70);
            CP16(sbase + kb * BSTAGE + sw,
                 &g_xh[(size_t)(n0 + r) * E_DIM + kb * KB + c8 * 8]);
        }
    }
    CP_COMMIT();
#pragma unroll
    for (int pp = 0; pp < 2; pp++) {
#pragma unroll
        for (int jj = 0; jj < 2; jj++) {
            int j = pp * 2 + jj;                 // tiles 0..3: q0=0, kb=j
#pragma unroll
            for (int i = 0; i < 4; i++) {
                int idx = tid + i * THREADS;
                int r = idx >> 3, c8 = idx & 7;
                uint32_t off = r * 128 + c8 * 16;
                uint32_t sw = off ^ ((off >> 3) & 0x70);
                CP16(bbase + (j % NSTAGE) * BSTAGE + sw,
                     &g_wh[(size_t)r * E_DIM + j * KB + c8 * 8]);
            }
        }
        CP_COMMIT();                             // one group per pair
    }

    // ldmatrix base offsets (XOR the ks*32 k-step into the swizzled address).
    uint32_t aOff[2], bOff[4];
#pragma unroll
    for (int mt = 0; mt < 2; mt++) {
        int row = wm * 32 + mt * 16 + (lane & 15);
        int kc  = (lane & 16) ? 16 : 0;
        uint32_t off = row * 128 + kc;
        aOff[mt] = off ^ ((off >> 3) & 0x70);
    }
#pragma unroll
    for (int bt = 0; bt < 4; bt++) {
        int row = wn * 64 + bt * 16 + ((lane & 16) ? 8 : 0) + (lane & 7);
        int kc  = (lane & 8) ? 16 : 0;
        uint32_t off = row * 128 + kc;
        bOff[bt] = off ^ ((off >> 3) & 0x70);
    }

    const int rbase = wm * 32 + (lane >> 2);
    const int cbase = wn * 64 + 2 * (lane & 3);
    const int TOTAL = (Q / NQ_T) * 8;           // 512 B tiles
    const int PAIRS = TOTAL / 2;                // 256

    float acc[2][8][4];

    for (int p = 0; p < PAIRS; p++) {
        const int j0 = 2 * p;                   // pair always within one chunk
        const int qc = j0 >> 3;
        const int q0 = qc * NQ_T;
        const int kb0 = j0 & 7;

        if (p + 1 < PAIRS) CP_WAIT1(); else CP_WAIT0();
        __syncthreads();

        if (kb0 == 0) {
            if (tid < NQ_T) wsq_s[tid] = g_wsq[q0 + tid];
#pragma unroll
            for (int mt = 0; mt < 2; mt++)
#pragma unroll
                for (int nt = 0; nt < 8; nt++)
#pragma unroll
                    for (int k = 0; k < 4; k++) acc[mt][nt][k] = 0.f;
        }

        // issue pair p+2 (stages consumed at pair p-1; sync-protected)
        if (p + 2 < PAIRS) {
#pragma unroll
            for (int jj = 0; jj < 2; jj++) {
                const int j = 2 * (p + 2) + jj;
                const int jq0 = (j >> 3) * NQ_T;
                const int jkb = j & 7;
                const uint32_t st = bbase + (j % NSTAGE) * BSTAGE;
#pragma unroll
                for (int i = 0; i < 4; i++) {
                    int idx = tid + i * THREADS;
                    int r = idx >> 3, c8 = idx & 7;
                    uint32_t off = r * 128 + c8 * 16;
                    uint32_t sw = off ^ ((off >> 3) & 0x70);
                    CP16(st + sw,
                         &g_wh[(size_t)(jq0 + r) * E_DIM + jkb * KB + c8 * 8]);
                }
            }
            CP_COMMIT();
        }

        // ---- mma on tiles j0 and j0+1 ----
#pragma unroll
        for (int jj = 0; jj < 2; jj++) {
            const int j = j0 + jj;
            const uint32_t aB = sbase + (j & 7) * BSTAGE;
            const uint32_t bB = bbase + (j % NSTAGE) * BSTAGE;
#pragma unroll
            for (int ks = 0; ks < 4; ks++) {
                uint32_t af[2][4];
#pragma unroll
                for (int mt = 0; mt < 2; mt++)
                    ldsm4(af[mt][0], af[mt][1], af[mt][2], af[mt][3],
                          aB + (aOff[mt] ^ (ks * 32)));
                uint32_t bf[4][4];
#pragma unroll
                for (int bt = 0; bt < 4; bt++)
                    ldsm4(bf[bt][0], bf[bt][1], bf[bt][2], bf[bt][3],
                          bB + (bOff[bt] ^ (ks * 32)));
#pragma unroll
                for (int mt = 0; mt < 2; mt++)
#pragma unroll
                    for (int nt = 0; nt < 8; nt++)
                        mma16816(acc[mt][nt], af[mt],
                                 bf[nt >> 1][(nt & 1) * 2],
                                 bf[nt >> 1][(nt & 1) * 2 + 1]);
            }
        }

        if (kb0 == 6) {
            // ---- epilogue (tile j0+1 had kb==7): dist, row-min, capture ----
            float lmin[4] = {3.4e38f, 3.4e38f, 3.4e38f, 3.4e38f};
#pragma unroll
            for (int mt = 0; mt < 2; mt++) {
                float xa = xsq_s[rbase + mt * 16];
                float xb = xsq_s[rbase + mt * 16 + 8];
#pragma unroll
                for (int nt = 0; nt < 8; nt++) {
                    float* c = acc[mt][nt];
                    int col = cbase + nt * 8;
                    float wa = wsq_s[col], wb = wsq_s[col + 1];
                    float d0 = xa + wa - 2.f * c[0];
                    float d1 = xa + wb - 2.f * c[1];
                    float d2 = xb + wa - 2.f * c[2];
                    float d3 = xb + wb - 2.f * c[3];
                    c[0] = d0; c[1] = d1; c[2] = d2; c[3] = d3;
                    lmin[mt * 2]     = fminf(lmin[mt * 2],     fminf(d0, d1));
                    lmin[mt * 2 + 1] = fminf(lmin[mt * 2 + 1], fminf(d2, d3));
                }
            }
#pragma unroll
            for (int g = 0; g < 4; g++) {
                int row = rbase + (g >> 1) * 16 + (g & 1) * 8;
                atomicMin(&rows_min[row], __float_as_int(lmin[g]));
            }
            __syncthreads();

#pragma unroll
            for (int mt = 0; mt < 2; mt++) {
#pragma unroll
                for (int g = 0; g < 2; g++) {
                    int row = rbase + mt * 16 + g * 8;
                    float thr = __int_as_float(rows_min[row]) + MARGIN;
                    if (lmin[mt * 2 + g] <= thr) {
#pragma unroll
                        for (int nt = 0; nt < 8; nt++) {
                            float da = acc[mt][nt][g * 2];
                            float db = acc[mt][nt][g * 2 + 1];
                            int col = cbase + nt * 8;
                            if (da <= thr) {
                                int pidx = atomicAdd(&cand_cnt[row], 1);
                                if (pidx < CAND_CAP)
                                    g_cand[(size_t)(n0 + row) * CAND_CAP + pidx] = q0 + col;
                            }
                            if (db <= thr) {
                                int pidx = atomicAdd(&cand_cnt[row], 1);
                                if (pidx < CAND_CAP)
                                    g_cand[(size_t)(n0 + row) * CAND_CAP + pidx] = q0 + col + 1;
                            }
                        }
                    }
                }
            }
            // next loop-top __syncthreads orders capture vs wsq_s overwrite
        }
    }

    __syncthreads();
    if (tid < M_T) g_ccnt[n0 + tid] = cand_cnt[tid];
}

// ---------------------------------------------------------------------------
// Exact rescore (reference-rounded) + gather. One warp per row.
// ---------------------------------------------------------------------------
__device__ __forceinline__ float warp_dot512(const float* __restrict__ xr,
                                             const float* __restrict__ wr,
                                             int lane)
{
    float s = 0.f;
#pragma unroll
    for (int k = 0; k < 16; k++)
        s = __fmaf_rn(xr[lane + k * 32], wr[lane + k * 32], s);
#pragma unroll
    for (int o = 16; o; o >>= 1) s += __shfl_xor_sync(0xffffffffu, s, o);
    return s;
}

__global__ __launch_bounds__(256) void rescore_kernel(
    const float* __restrict__ x, const float* __restrict__ w,
    float* __restrict__ out, float* __restrict__ out_idx,
    int write_idx, int Q)
{
    const int lane = threadIdx.x & 31;
    const int row  = blockIdx.x * 8 + (threadIdx.x >> 5);
    const float xsq = g_xsq[row];
    const float* xr = x + (size_t)row * E_DIM;

    float best = 3.4e38f;
    int   bq   = 0x7fffffff;
    int cnt = g_ccnt[row];

    if (cnt <= CAND_CAP) {
        for (int i = 0; i < cnt; i++) {
            int q = g_cand[(size_t)row * CAND_CAP + i];
            float xw = warp_dot512(xr, w + (size_t)q * E_DIM, lane);
            float t1 = __fadd_rn(xsq, -__fmul_rn(2.0f, xw));
            float d  = __fadd_rn(t1, g_wsq[q]);
            if (d < best || (d == best && q < bq)) { best = d; bq = q; }
        }
    } else {
        // overflow fallback (unreachable in practice): exact full scan.
        for (int q = 0; q < Q; q++) {
            float xw = warp_dot512(xr, w + (size_t)q * E_DIM, lane);
            float t1 = __fadd_rn(xsq, -__fmul_rn(2.0f, xw));
            float d  = __fadd_rn(t1, g_wsq[q]);
            if (d < best) { best = d; bq = q; }
        }
    }

    if (write_idx && lane == 0) out_idx[row] = (float)bq;

    const float4* wr4 = (const float4*)(w + (size_t)bq * E_DIM);
    float4* o4 = (float4*)(out + (size_t)row * E_DIM);
#pragma unroll
    for (int c = lane; c < E_DIM / 4; c += 32) o4[c] = wr4[c];
}

// ---------------------------------------------------------------------------
extern "C" void kernel_launch(void* const* d_in, const int* in_sizes, int n_in,
                              void* d_out, int out_size)
{
    const float* x = (const float*)d_in[0];
    const float* w = (const float*)d_in[1];
    float* out = (float*)d_out;

    const int E = E_DIM;
    const int N = in_sizes[0] / E;   // 16384
    const int Q = in_sizes[1] / E;   // 8192

    const long long NE = (long long)N * E;
    int write_idx = (out_size >= NE + N) ? 1 : 0;
    float* out_idx = out + NE;

    cudaFuncSetAttribute(vq_approx_kernel,
                         cudaFuncAttributeMaxDynamicSharedMemorySize, DSMEM_BYTES);

    prep_kernel<<<N / 128 + Q / 128, 128>>>(x, w, N / 128);
    vq_approx_kernel<<<N / M_T, THREADS, DSMEM_BYTES>>>(Q);
    rescore_kernel<<<N / 8, 256>>>(x, w, out, out_idx, write_idx, Q);
}